// round 15
// baseline (speedup 1.0000x reference)
#include <cuda_runtime.h>
#include <cuda_fp16.h>
#include <cstdint>

#define SQ    2048
#define HDM   2048
#define NH    32
#define NKV   4
#define HD    128
#define NE    16
#define ID    768
#define TOPK  4
#define NSLOT (SQ*TOPK)
#define QKVN  (NH*HD + 2*NKV*HD)   // 5120
#define GUN   (2*ID)               // 1536
#define WSC   64.0f
#define WSCI  (1.0f/64.0f)

typedef __half h16;

// ---------------- device scratch -------------------------------------------
__device__ __align__(16) h16 g_wqkv_h[(size_t)QKVN*HDM],  g_wqkv_l[(size_t)QKVN*HDM];
__device__ __align__(16) h16 g_wo_h[(size_t)HDM*NH*HD],   g_wo_l[(size_t)HDM*NH*HD];
__device__ __align__(16) h16 g_wgu_h[(size_t)NE*GUN*HDM];
__device__ __align__(16) h16 g_wd_h[(size_t)NE*HDM*ID];
__device__ __align__(16) h16 g_xn_h[(size_t)SQ*HDM],      g_xn_l[(size_t)SQ*HDM];
__device__ __align__(16) float g_qkvlin[(size_t)SQ*QKVN];
__device__ __align__(16) h16 g_qh_h[(size_t)NH*SQ*HD],    g_qh_l[(size_t)NH*SQ*HD];
__device__ __align__(16) h16 g_kh_h[(size_t)NKV*SQ*HD],   g_kh_l[(size_t)NKV*SQ*HD];
__device__ __align__(16) h16 g_vt_h[(size_t)NKV*HD*SQ],   g_vt_l[(size_t)NKV*HD*SQ];
__device__ __align__(16) h16 g_ao_h[(size_t)SQ*NH*HD],    g_ao_l[(size_t)SQ*NH*HD];
__device__ __align__(16) float g_res[SQ*HDM];
__device__ __align__(16) float g_h2f[SQ*HDM];
__device__ __align__(16) h16 g_h2_h[(size_t)SQ*HDM];
__device__ __align__(16) h16 g_gu[(size_t)NSLOT*GUN];
__device__ __align__(16) h16 g_g_h[(size_t)NSLOT*ID];
__device__ __align__(16) h16 g_ybuf[(size_t)NSLOT*HDM];
__device__ int   g_tidx[NSLOT];
__device__ float g_trw[NSLOT];
__device__ int   g_counts[NE];
__device__ int   g_offs[NE];
__device__ int   g_token_of[NSLOT];
__device__ int   g_slot_of[NSLOT];

// ---------------- helpers ----------------------------------------------------
__device__ __forceinline__ void splitf(float v, h16& h, h16& l) {
    h = __float2half(v);
    l = __float2half(v - __half2float(h));
}
__device__ __forceinline__ uint32_t pack2h(h16 a, h16 b) {
    __half2 t(a, b);
    return *(uint32_t*)&t;
}
__device__ __forceinline__ void ldsm4(uint32_t r[4], uint32_t addr) {
    asm volatile("ldmatrix.sync.aligned.m8n8.x4.shared.b16 {%0,%1,%2,%3},[%4];"
        : "=r"(r[0]), "=r"(r[1]), "=r"(r[2]), "=r"(r[3]) : "r"(addr));
}
__device__ __forceinline__ void mma16816(float c[4], const uint32_t a[4], const uint32_t b[2]) {
    asm volatile("mma.sync.aligned.m16n8k16.row.col.f32.f16.f16.f32 "
        "{%0,%1,%2,%3},{%4,%5,%6,%7},{%8,%9},{%0,%1,%2,%3};"
        : "+f"(c[0]), "+f"(c[1]), "+f"(c[2]), "+f"(c[3])
        : "r"(a[0]), "r"(a[1]), "r"(a[2]), "r"(a[3]), "r"(b[0]), "r"(b[1]));
}
__device__ __forceinline__ void cp16(uint32_t dst, const void* src, int sz) {
    asm volatile("cp.async.cg.shared.global [%0],[%1],16,%2;\n" :: "r"(dst), "l"(src), "r"(sz));
}
__device__ __forceinline__ void cp_commit() { asm volatile("cp.async.commit_group;\n"); }
__device__ __forceinline__ void cp_wait1() { asm volatile("cp.async.wait_group 1;\n"); }

__device__ __forceinline__ float blockReduceSum(float v) {
    __shared__ float sh[8];
    int lane = threadIdx.x & 31, w = threadIdx.x >> 5;
    #pragma unroll
    for (int o = 16; o; o >>= 1) v += __shfl_xor_sync(0xffffffffu, v, o);
    if (lane == 0) sh[w] = v;
    __syncthreads();
    float r = (threadIdx.x < (blockDim.x >> 5)) ? sh[threadIdx.x] : 0.f;
    if (w == 0) {
        #pragma unroll
        for (int o = 4; o; o >>= 1) r += __shfl_xor_sync(0xffffffffu, r, o);
        if (lane == 0) sh[0] = r;
    }
    __syncthreads();
    r = sh[0];
    __syncthreads();
    return r;
}

// ---------------- weight split conversions (weights pre-scaled by WSC) ----------
__global__ void split_kernel(const float* __restrict__ in, h16* __restrict__ hi,
                             h16* __restrict__ lo, size_t n) {
    size_t base = (size_t)blockIdx.x * 4096 + threadIdx.x * 4;
    #pragma unroll
    for (int u = 0; u < 4; u++) {
        size_t i = base + u * 1024;
        if (i >= n) return;
        float4 v = *(const float4*)(in + i);
        h16 h0, l0, h1, l1, h2, l2, h3, l3;
        splitf(v.x * WSC, h0, l0); splitf(v.y * WSC, h1, l1);
        splitf(v.z * WSC, h2, l2); splitf(v.w * WSC, h3, l3);
        *(__half2*)(hi + i)     = __half2(h0, h1);
        *(__half2*)(hi + i + 2) = __half2(h2, h3);
        if (lo) {
            *(__half2*)(lo + i)     = __half2(l0, l1);
            *(__half2*)(lo + i + 2) = __half2(l2, l3);
        }
    }
}

__global__ void split_gu_kernel(const float* __restrict__ gp, const float* __restrict__ up,
                                h16* __restrict__ hi) {
    size_t base = (size_t)blockIdx.x * 4096 + threadIdx.x * 4;
    #pragma unroll
    for (int u = 0; u < 4; u++) {
        size_t i = base + u * 1024;
        if (i >= (size_t)NE * ID * HDM) return;
        size_t e = i / ((size_t)ID * HDM);
        size_t rem = i - e * (size_t)ID * HDM;
        size_t dg = e * (size_t)GUN * HDM + rem;
        size_t du = dg + (size_t)ID * HDM;
        float4 vg = *(const float4*)(gp + i);
        float4 vu = *(const float4*)(up + i);
        *(__half2*)(hi + dg)     = __half2(__float2half(vg.x * WSC), __float2half(vg.y * WSC));
        *(__half2*)(hi + dg + 2) = __half2(__float2half(vg.z * WSC), __float2half(vg.w * WSC));
        *(__half2*)(hi + du)     = __half2(__float2half(vu.x * WSC), __float2half(vu.y * WSC));
        *(__half2*)(hi + du + 2) = __half2(__float2half(vu.z * WSC), __float2half(vu.w * WSC));
    }
}

// ---------------- rms norm (vectorized, ncols fixed at 2048, 256 thr) ------------
__global__ void rmsnorm_kernel(const float* __restrict__ x, const float* __restrict__ w,
                               float* __restrict__ outf, h16* __restrict__ oh,
                               h16* __restrict__ ol, int ncols) {
    size_t base = (size_t)blockIdx.x * 2048;
    int i0 = threadIdx.x * 4;
    float4 a = *(const float4*)(x + base + i0);
    float4 b = *(const float4*)(x + base + i0 + 1024);
    float ss = a.x*a.x + a.y*a.y + a.z*a.z + a.w*a.w
             + b.x*b.x + b.y*b.y + b.z*b.z + b.w*b.w;
    ss = blockReduceSum(ss);
    float r = rsqrtf(ss * (1.f / 2048.f) + 1e-6f);
    float4 wa = *(const float4*)(w + i0);
    float4 wb = *(const float4*)(w + i0 + 1024);
    float va[8] = {wa.x*a.x*r, wa.y*a.y*r, wa.z*a.z*r, wa.w*a.w*r,
                   wb.x*b.x*r, wb.y*b.y*r, wb.z*b.z*r, wb.w*b.w*r};
    if (outf) {
        *(float4*)(outf + base + i0)        = make_float4(va[0], va[1], va[2], va[3]);
        *(float4*)(outf + base + i0 + 1024) = make_float4(va[4], va[5], va[6], va[7]);
    }
    if (oh) {
        h16 h[8], l[8];
        #pragma unroll
        for (int k = 0; k < 8; k++) splitf(va[k], h[k], l[k]);
        *(__half2*)(oh + base + i0)            = __half2(h[0], h[1]);
        *(__half2*)(oh + base + i0 + 2)        = __half2(h[2], h[3]);
        *(__half2*)(oh + base + i0 + 1024)     = __half2(h[4], h[5]);
        *(__half2*)(oh + base + i0 + 1026)     = __half2(h[6], h[7]);
        if (ol) {
            *(__half2*)(ol + base + i0)        = __half2(l[0], l[1]);
            *(__half2*)(ol + base + i0 + 2)    = __half2(l[2], l[3]);
            *(__half2*)(ol + base + i0 + 1024) = __half2(l[4], l[5]);
            *(__half2*)(ol + base + i0 + 1026) = __half2(l[6], l[7]);
        }
    }
}

// ---------------- per-head rmsnorm + rope (Q and K fused in one grid) --------------
__global__ void norm_rope_kernel(const float* __restrict__ lin,
                                 const float* __restrict__ qnw, const float* __restrict__ knw,
                                 const float* __restrict__ pe,
                                 h16* __restrict__ qh, h16* __restrict__ ql,
                                 h16* __restrict__ kh, h16* __restrict__ kl) {
    int t = blockIdx.x, hh = blockIdx.y, d = threadIdx.x;
    bool isq = hh < NH;
    int colbase = isq ? hh * HD : (NH * HD + (hh - NH) * HD);
    const float* nw = isq ? qnw : knw;
    float v = lin[(size_t)t * QKVN + colbase + d];
    float ss = v * v;
    #pragma unroll
    for (int o = 16; o; o >>= 1) ss += __shfl_xor_sync(0xffffffffu, ss, o);
    __shared__ float wsum[4];
    if ((d & 31) == 0) wsum[d >> 5] = ss;
    __syncthreads();
    float tot = wsum[0] + wsum[1] + wsum[2] + wsum[3];
    float xn = nw[d] * v * rsqrtf(tot * (1.f / HD) + 1e-6f);
    __shared__ float sh[HD];
    sh[d] = xn;
    __syncthreads();
    float c = pe[(size_t)t * HD + d];
    float s = pe[(size_t)SQ * HD + (size_t)t * HD + d];
    float rot = (d < HD / 2) ? -sh[d + HD / 2] : sh[d - HD / 2];
    float o = xn * c + rot * s;
    h16 ho, lo; splitf(o, ho, lo);
    if (isq) {
        size_t idx = ((size_t)hh * SQ + t) * HD + d;
        qh[idx] = ho; ql[idx] = lo;
    } else {
        size_t idx = ((size_t)(hh - NH) * SQ + t) * HD + d;
        kh[idx] = ho; kl[idx] = lo;
    }
}

// ---------------- V transpose + split, coalesced via smem tile -------------------
__global__ void vtrans_kernel(const float* __restrict__ qkvlin, h16* __restrict__ vh,
                              h16* __restrict__ vl) {
    __shared__ float tile[32][33];
    int kv = blockIdx.z;
    int t0 = blockIdx.x * 32, d0 = blockIdx.y * 32;
    int tx = threadIdx.x, ty = threadIdx.y;
    #pragma unroll
    for (int i = ty; i < 32; i += 8)
        tile[i][tx] = qkvlin[(size_t)(t0 + i) * QKVN + (NH * HD + NKV * HD) + kv * HD + d0 + tx];
    __syncthreads();
    #pragma unroll
    for (int i = ty; i < 32; i += 8) {
        float v = tile[tx][i];
        h16 h, l; splitf(v, h, l);
        size_t idx = ((size_t)kv * HD + d0 + i) * SQ + t0 + tx;
        vh[idx] = h; vl[idx] = l;
    }
}

// =================================================================================
// fp16 mma.sync GEMM, 2-stage cp.async, 2 CTAs/SM (R13 binding config).
// NS=3 (hi/lo x3 split) or NS=1 (single stream).
// MODE 0 dense / 1 gather rows / 2 direct ragged rows
// EPI 0 fp32*cscale / 2 fp32*cscale+residual / 5 fp16*cscale
// =================================================================================
#define BM 128
#define BN 128
#define BK 32
#define BKP 40
#define TILE_HALF (BM * BKP)

template<int EPI, int MODE, int NS>
__global__ void __launch_bounds__(256, 2) gemm_mma(
    const h16* __restrict__ Ah, const h16* __restrict__ Al, int lda, long sAz,
    const h16* __restrict__ Bh, const h16* __restrict__ Bl, int ldb, long sBz,
    float* __restrict__ Cf, h16* __restrict__ Chf, int ldc, long sCz,
    int K, float cscale, const float* __restrict__ epi, int lde,
    const int* __restrict__ counts, const int* __restrict__ offs,
    const int* __restrict__ token_of)
{
    constexpr uint32_t STB = (uint32_t)((NS == 3 ? 4 : 2) * TILE_HALF * 2);
    constexpr uint32_t OFF_AL = TILE_HALF * 2;
    constexpr uint32_t OFF_BH = (NS == 3 ? 2 : 1) * TILE_HALF * 2;
    constexpr uint32_t OFF_BL = 3 * TILE_HALF * 2;

    int z = blockIdx.z;
    int m0 = blockIdx.y * BM, n0 = blockIdx.x * BN;
    int Me = 0x7fffffff, off = 0;
    if (MODE != 0) { Me = counts[z]; if (m0 >= Me) return; off = offs[z]; }
    int nkt = K / BK;

    const h16* Ahp = Ah; const h16* Alp = Al;
    if (MODE == 0) { Ahp += (size_t)z * sAz; if (NS == 3) Alp += (size_t)z * sAz; }
    const h16* Bhp = Bh + (size_t)z * sBz;
    const h16* Blp = (NS == 3) ? (Bl + (size_t)z * sBz) : nullptr;

    extern __shared__ h16 smem[];
    uint32_t sbase = (uint32_t)__cvta_generic_to_shared(smem);

    int tid = threadIdx.x;
    int lr = tid >> 2;
    int lc = (tid & 3) * 8;

    int rl0 = m0 + lr, rl1 = m0 + lr + 64;
    bool av0 = true, av1 = true;
    size_t ar0, ar1;
    if (MODE == 1) {
        av0 = rl0 < Me; av1 = rl1 < Me;
        ar0 = av0 ? (size_t)token_of[off + rl0] : 0;
        ar1 = av1 ? (size_t)token_of[off + rl1] : 0;
    } else if (MODE == 2) {
        av0 = rl0 < Me; av1 = rl1 < Me;
        ar0 = av0 ? (size_t)(off + rl0) : 0;
        ar1 = av1 ? (size_t)(off + rl1) : 0;
    } else { ar0 = rl0; ar1 = rl1; }
    size_t offA0 = ar0 * (size_t)lda + lc;
    size_t offA1 = ar1 * (size_t)lda + lc;
    size_t offB0 = (size_t)(n0 + lr) * ldb + lc;
    size_t offB1 = (size_t)(n0 + lr + 64) * ldb + lc;
    int sz0 = av0 ? 16 : 0, sz1 = av1 ? 16 : 0;

    uint32_t dA0 = sbase + (lr * BKP + lc) * 2;
    uint32_t dA1 = sbase + ((lr + 64) * BKP + lc) * 2;

    const int warp = tid >> 5, lane = tid & 31;
    const int wm = (warp >> 1) * 32;
    const int wn = (warp & 1) * 64;
    const int ldr = lane & 15;
    const int ldc8 = (lane >> 4) * 8;

    float acc[2][8][4];
    #pragma unroll
    for (int i = 0; i < 2; i++)
        #pragma unroll
        for (int j = 0; j < 8; j++)
            #pragma unroll
            for (int q = 0; q < 4; q++) acc[i][j][q] = 0.f;

    #define LOAD_STAGE(kt) do {                                          \
        uint32_t nb = (uint32_t)((kt) & 1) * STB;                         \
        int k0_ = (kt) * BK;                                              \
        cp16(dA0 + nb, Ahp + offA0 + k0_, sz0);                           \
        cp16(dA1 + nb, Ahp + offA1 + k0_, sz1);                           \
        cp16(dA0 + nb + OFF_BH, Bhp + offB0 + k0_, 16);                   \
        cp16(dA1 + nb + OFF_BH, Bhp + offB1 + k0_, 16);                   \
        if (NS == 3) {                                                    \
            cp16(dA0 + nb + OFF_AL, Alp + offA0 + k0_, sz0);              \
            cp16(dA1 + nb + OFF_AL, Alp + offA1 + k0_, sz1);              \
            cp16(dA0 + nb + OFF_BL, Blp + offB0 + k0_, 16);               \
            cp16(dA1 + nb + OFF_BL, Blp + offB1 + k0_, 16);               \
        }                                                                 \
    } while (0)

    LOAD_STAGE(0);
    cp_commit();

    for (int kt = 0; kt < nkt; kt++) {
        if (kt + 1 < nkt) LOAD_STAGE(kt + 1);
        cp_commit();
        cp_wait1();
        __syncthreads();

        uint32_t bA = sbase + (uint32_t)(kt & 1) * STB;
        #pragma unroll
        for (int ks = 0; ks < 2; ks++) {
            int kk = ks * 16 + ldc8;
            uint32_t ah[2][4], al[2][4], bh[8][2], bl[8][2];
            #pragma unroll
            for (int mt = 0; mt < 2; mt++) {
                uint32_t adr = ((wm + mt * 16 + ldr) * BKP + kk) * 2;
                ldsm4(ah[mt], bA + adr);
                if (NS == 3) ldsm4(al[mt], bA + OFF_AL + adr);
            }
            #pragma unroll
            for (int np = 0; np < 4; np++) {
                uint32_t adr = ((wn + np * 16 + ldr) * BKP + kk) * 2;
                uint32_t r[4];
                ldsm4(r, bA + OFF_BH + adr);
                bh[np*2][0] = r[0]; bh[np*2+1][0] = r[1]; bh[np*2][1] = r[2]; bh[np*2+1][1] = r[3];
                if (NS == 3) {
                    ldsm4(r, bA + OFF_BL + adr);
                    bl[np*2][0] = r[0]; bl[np*2+1][0] = r[1]; bl[np*2][1] = r[2]; bl[np*2+1][1] = r[3];
                }
            }
            #pragma unroll
            for (int mt = 0; mt < 2; mt++)
                #pragma unroll
                for (int nt = 0; nt < 8; nt++) {
                    mma16816(acc[mt][nt], ah[mt], bh[nt]);
                    if (NS == 3) {
                        mma16816(acc[mt][nt], ah[mt], bl[nt]);
                        mma16816(acc[mt][nt], al[mt], bh[nt]);
                    }
                }
        }
        __syncthreads();
    }
    #undef LOAD_STAGE

    int er = lane >> 2;
    int ec = (lane & 3) * 2;
    #pragma unroll
    for (int mt = 0; mt < 2; mt++) {
        #pragma unroll
        for (int h = 0; h < 2; h++) {
            int mloc = m0 + wm + mt * 16 + h * 8 + er;
            bool mvalid = (MODE == 0) || (mloc < Me);
            if (!mvalid) continue;
            size_t crow = (MODE == 0) ? (size_t)mloc : (size_t)(off + mloc);
            #pragma unroll
            for (int nt = 0; nt < 8; nt++) {
                int col = n0 + wn + nt * 8 + ec;
                float v0 = acc[mt][nt][h * 2 + 0] * cscale;
                float v1 = acc[mt][nt][h * 2 + 1] * cscale;
                size_t ci = (size_t)z * sCz + crow * ldc + col;
                if (EPI == 5) {
                    *(__half2*)(Chf + ci) = __half2(__float2half(v0), __float2half(v1));
                } else {
                    if (EPI == 2) {
                        float2 rr = *(const float2*)(epi + (size_t)mloc * lde + col);
                        v0 += rr.x; v1 += rr.y;
                    }
                    *(float2*)(Cf + ci) = make_float2(v0, v1);
                }
            }
        }
    }
}

// =================================================================================
// Fused flash attention: QK x3, PV x2 (P single fp16, V hi/lo). Reversed m order.
// =================================================================================
#define FQH 0
#define FQL 17408
#define FKOFF 34816
#define FVOFF 69632
#define FSMEM (106496 * 2)

__global__ void __launch_bounds__(256, 1) flash_kernel(
    const h16* __restrict__ qh_h, const h16* __restrict__ qh_l,
    const h16* __restrict__ kh_h, const h16* __restrict__ kh_l,
    const h16* __restrict__ vt_h, const h16* __restrict__ vt_l,
    h16* __restrict__ ao_h, h16* __restrict__ ao_l, float scale)
{
    int m0 = (gridDim.x - 1 - blockIdx.x) * 128;
    int h = blockIdx.y;
    int kvh = h >> 3;

    extern __shared__ h16 fsm[];
    uint32_t sb = (uint32_t)__cvta_generic_to_shared(fsm);

    int tid = threadIdx.x, wid = tid >> 5, lane = tid & 31;
    const int ldr = lane & 15, ldc8 = (lane >> 4) * 8;

    {
        const h16* qs_h = qh_h + ((size_t)h * SQ + m0) * HD;
        const h16* qs_l = qh_l + ((size_t)h * SQ + m0) * HD;
        for (int c = tid; c < 2048; c += 256) {
            int r = c >> 4, col = (c & 15) * 8;
            size_t go = (size_t)r * HD + col;
            cp16(sb + (uint32_t)(FQH + r * 136 + col) * 2, qs_h + go, 16);
            cp16(sb + (uint32_t)(FQL + r * 136 + col) * 2, qs_l + go, 16);
        }
    }
    cp_commit();

    int nj = (m0 + 128) >> 6;

    #define LOAD_KV(jj, stg) do {                                                     \
        for (int c = tid; c < 1024; c += 256) {                                        \
            int kr = c >> 4, kc = (c & 15) * 8;                                        \
            size_t kgo = ((size_t)kvh * SQ + (jj) * 64 + kr) * HD + kc;                \
            uint32_t kd = sb + (uint32_t)(FKOFF + (stg) * 17408 + kr * 136 + kc) * 2;  \
            cp16(kd, kh_h + kgo, 16);                                                  \
            cp16(kd + 8704 * 2, kh_l + kgo, 16);                                       \
            int vr = c >> 3, vc = (c & 7) * 8;                                         \
            size_t vgo = ((size_t)kvh * HD + vr) * SQ + (jj) * 64 + vc;                \
            cp16(sb + (uint32_t)(FVOFF + (stg) * 18432 + vr * 72 + vc) * 2, vt_h + vgo, 16); \
            cp16(sb + (uint32_t)(FVOFF + (stg) * 18432 + vr * 72 + vc) * 2 + 9216 * 2, vt_l + vgo, 16); \
        }                                                                               \
    } while (0)

    LOAD_KV(0, 0);
    cp_commit();

    int rbase = wid * 16;
    float m_r0 = -1e30f, m_r1 = -1e30f, l_r0 = 0.f, l_r1 = 0.f;
    float o[16][4];
    #pragma unroll
    for (int i = 0; i < 16; i++)
        #pragma unroll
        for (int q = 0; q < 4; q++) o[i][q] = 0.f;

    int grow0 = m0 + rbase + (lane >> 2);
    int ar = rbase + ldr;

    for (int j = 0; j < nj; j++) {
        if (j + 1 < nj) LOAD_KV(j + 1, (j + 1) & 1);
        cp_commit();
        cp_wait1();
        __syncthreads();

        bool skip = (j * 64 > m0 + rbase + 15);
        if (!skip) {
            int st = j & 1;
            uint32_t kst = (uint32_t)(FKOFF + st * 17408);
            uint32_t vst = (uint32_t)(FVOFF + st * 18432);

            float s[8][4];
            #pragma unroll
            for (int nt = 0; nt < 8; nt++)
                #pragma unroll
                for (int q = 0; q < 4; q++) s[nt][q] = 0.f;

            #pragma unroll
            for (int kt = 0; kt < 8; kt++) {
                int kk = kt * 16 + ldc8;
                uint32_t aqh[4], aql[4];
                ldsm4(aqh, sb + (uint32_t)(FQH + ar * 136 + kk) * 2);
                ldsm4(aql, sb + (uint32_t)(FQL + ar * 136 + kk) * 2);
                #pragma unroll
                for (int np = 0; np < 4; np++) {
                    uint32_t kadr = sb + (kst + (np * 16 + ldr) * 136 + kk) * 2;
                    uint32_t rh[4], rl[4];
                    ldsm4(rh, kadr);
                    ldsm4(rl, kadr + 8704 * 2);
                    uint32_t b0h[2] = {rh[0], rh[2]}, b1h[2] = {rh[1], rh[3]};
                    uint32_t b0l[2] = {rl[0], rl[2]}, b1l[2] = {rl[1], rl[3]};
                    mma16816(s[np*2],   aqh, b0h);
                    mma16816(s[np*2],   aqh, b0l);
                    mma16816(s[np*2],   aql, b0h);
                    mma16816(s[np*2+1], aqh, b1h);
                    mma16816(s[np*2+1], aqh, b1l);
                    mma16816(s[np*2+1], aql, b1h);
                }
            }

            float mx0 = -1e30f, mx1 = -1e30f;
            #pragma unroll
            for (int nt = 0; nt < 8; nt++) {
                int gc = j * 64 + nt * 8 + (lane & 3) * 2;
                float v0 = s[nt][0] * scale; if (gc     > grow0)     v0 = -1e30f;
                float v1 = s[nt][1] * scale; if (gc + 1 > grow0)     v1 = -1e30f;
                float v2 = s[nt][2] * scale; if (gc     > grow0 + 8) v2 = -1e30f;
                float v3 = s[nt][3] * scale; if (gc + 1 > grow0 + 8) v3 = -1e30f;
                s[nt][0] = v0; s[nt][1] = v1; s[nt][2] = v2; s[nt][3] = v3;
                mx0 = fmaxf(mx0, fmaxf(v0, v1));
                mx1 = fmaxf(mx1, fmaxf(v2, v3));
            }
            mx0 = fmaxf(mx0, __shfl_xor_sync(0xffffffffu, mx0, 1));
            mx0 = fmaxf(mx0, __shfl_xor_sync(0xffffffffu, mx0, 2));
            mx1 = fmaxf(mx1, __shfl_xor_sync(0xffffffffu, mx1, 1));
            mx1 = fmaxf(mx1, __shfl_xor_sync(0xffffffffu, mx1, 2));
            float mn0 = fmaxf(m_r0, mx0), mn1 = fmaxf(m_r1, mx1);
            float al0 = __expf(m_r0 - mn0), al1 = __expf(m_r1 - mn1);
            float sm0 = 0.f, sm1 = 0.f;
            #pragma unroll
            for (int nt = 0; nt < 8; nt++) {
                float p0 = __expf(s[nt][0] - mn0);
                float p1 = __expf(s[nt][1] - mn0);
                float p2 = __expf(s[nt][2] - mn1);
                float p3 = __expf(s[nt][3] - mn1);
                s[nt][0] = p0; s[nt][1] = p1; s[nt][2] = p2; s[nt][3] = p3;
                sm0 += p0 + p1; sm1 += p2 + p3;
            }
            sm0 += __shfl_xor_sync(0xffffffffu, sm0, 1);
            sm0 += __shfl_xor_sync(0xffffffffu, sm0, 2);
            sm1 += __shfl_xor_sync(0xffffffffu, sm1, 1);
            sm1 += __shfl_xor_sync(0xffffffffu, sm1, 2);
            l_r0 = l_r0 * al0 + sm0;
            l_r1 = l_r1 * al1 + sm1;
            m_r0 = mn0; m_r1 = mn1;
            #pragma unroll
            for (int i = 0; i < 16; i++) {
                o[i][0] *= al0; o[i][1] *= al0;
                o[i][2] *= al1; o[i][3] *= al1;
            }

            #pragma unroll
            for (int kt2 = 0; kt2 < 4; kt2++) {
                uint32_t ah[4];
                ah[0] = pack2h(__float2half(s[2*kt2][0]),   __float2half(s[2*kt2][1]));
                ah[1] = pack2h(__float2half(s[2*kt2][2]),   __float2half(s[2*kt2][3]));
                ah[2] = pack2h(__float2half(s[2*kt2+1][0]), __float2half(s[2*kt2+1][1]));
                ah[3] = pack2h(__float2half(s[2*kt2+1][2]), __float2half(s[2*kt2+1][3]));
                int kk2 = kt2 * 16 + ldc8;
                #pragma unroll
                for (int np = 0; np < 8; np++) {
                    uint32_t vadr = sb + (vst + (np * 16 + ldr) * 72 + kk2) * 2;
                    uint32_t rh[4], rl[4];
                    ldsm4(rh, vadr);
                    ldsm4(rl, vadr + 9216 * 2);
                    uint32_t b0h[2] = {rh[0], rh[2]}, b1h[2] = {rh[1], rh[3]};
                    uint32_t b0l[2] = {rl[0], rl[2]}, b1l[2] = {rl[1], rl[3]};
                    mma16816(o[np*2],   ah, b0h);
                    mma16816(o[np*2],   ah, b0l);
                    mma16816(o[np*2+1], ah, b1h);
                    mma16816(o[np*2+1], ah, b1l);
                }
            }
        }
        __syncthreads();
    }
    #undef LOAD_KV

    float inv0 = 1.f / l_r0, inv1 = 1.f / l_r1;
    int row0 = m0 + rbase + (lane >> 2);
    size_t base0 = (size_t)row0 * (NH * HD) + (size_t)h * HD;
    size_t base1 = base0 + (size_t)8 * (NH * HD);
    #pragma unroll
    for (int nt = 0; nt < 16; nt++) {
        int col = nt * 8 + (lane & 3) * 2;
        h16 h0, lo0, h1, lo1;
        splitf(o[nt][0] * inv0, h0, lo0); splitf(o[nt][1] * inv0, h1, lo1);
        *(__half2*)(ao_h + base0 + col) = __half2(h0, h1);
        *(__half2*)(ao_l + base0 + col) = __half2(lo0, lo1);
        splitf(o[nt][2] * inv1, h0, lo0); splitf(o[nt][3] * inv1, h1, lo1);
        *(__half2*)(ao_h + base1 + col) = __half2(h0, h1);
        *(__half2*)(ao_l + base1 + col) = __half2(lo0, lo1);
    }
}

// ---------------- router (smem-staged row, vectorized load) -------------------------
__global__ void gate_topk_kernel(const float* __restrict__ h2, const float* __restrict__ gw,
                                 int* __restrict__ oidx, float* __restrict__ orw) {
    int t = blockIdx.x;
    __shared__ float srow[HDM];
    const float* hr = h2 + (size_t)t * HDM;
    {
        int i0 = threadIdx.x * 4;
        *(float4*)(srow + i0)        = *(const float4*)(hr + i0);
        *(float4*)(srow + i0 + 1024) = *(const float4*)(hr + i0 + 1024);
    }
    __syncthreads();

    int e = threadIdx.x >> 4, l = threadIdx.x & 15;
    const float* wr = gw + (size_t)e * HDM;
    float p = 0.f;
    for (int k = l; k < HDM; k += 16) p += srow[k] * wr[k];
    #pragma unroll
    for (int o = 8; o; o >>= 1) p += __shfl_xor_sync(0xffffffffu, p, o);
    __shared__ float slog[NE];
    if (l == 0) slog[e] = p;
    __syncthreads();
    if (threadIdx.x == 0) {
        float pr[NE];
        float mx = -3.4e38f;
        for (int i = 0; i < NE; i++) { pr[i] = slog[i]; mx = fmaxf(mx, pr[i]); }
        float sum = 0.f;
        for (int i = 0; i < NE; i++) { pr[i] = __expf(pr[i] - mx); sum += pr[i]; }
        float inv = 1.f / sum;
        for (int i = 0; i < NE; i++) pr[i] *= inv;
        int sel[TOPK]; float sv[TOPK]; float wsum = 0.f;
        for (int k = 0; k < TOPK; k++) {
            int best = 0; float bv = -1.f;
            for (int i = 0; i < NE; i++)
                if (pr[i] > bv) { bv = pr[i]; best = i; }
            sel[k] = best; sv[k] = bv; wsum += bv; pr[best] = -2.f;
        }
        float winv = 1.f / wsum;
        for (int k = 0; k < TOPK; k++) { oidx[t * TOPK + k] = sel[k]; orw[t * TOPK + k] = sv[k] * winv; }
    }
}

// ---------------- deterministic routing sort ----------------------------------------
__global__ void route_kernel(const int* __restrict__ idx, int* __restrict__ counts,
                             int* __restrict__ offs, int* __restrict__ token_of,
                             int* __restrict__ slot_of) {
    int c = threadIdx.x;
    int start = c * (NSLOT / 32);
    int cnt[NE];
    #pragma unroll
    for (int e = 0; e < NE; e++) cnt[e] = 0;
    for (int i = 0; i < NSLOT / 32; i++) cnt[idx[start + i]]++;
    __shared__ int scnt[32][NE];
    __shared__ int sbase[32][NE];
    for (int e = 0; e < NE; e++) scnt[c][e] = cnt[e];
    __syncthreads();
    if (c == 0) {
        int off = 0;
        for (int e = 0; e < NE; e++) {
            offs[e] = off;
            int run = off;
            for (int cc = 0; cc < 32; cc++) { sbase[cc][e] = run; run += scnt[cc][e]; }
            counts[e] = run - off;
            off = run;
        }
    }
    __syncthreads();
    int base[NE];
    #pragma unroll
    for (int e = 0; e < NE; e++) base[e] = sbase[c][e];
    for (int i = 0; i < NSLOT / 32; i++) {
        int entry = start + i;
        int e = idx[entry];
        int pos = base[e]++;
        token_of[pos] = entry >> 2;
        slot_of[entry] = pos;
    }
}

// ---------------- silu(g)*u (fp16 in/out, vectorized) ---------------------------------
__global__ void silu_mul_kernel(const h16* __restrict__ gu, h16* __restrict__ gh) {
    int s = blockIdx.x;
    const h16* row = gu + (size_t)s * GUN;
    for (int i = threadIdx.x * 2; i < ID; i += 512) {
        __half2 g2 = *(const __half2*)(row + i);
        __half2 u2 = *(const __half2*)(row + ID + i);
        float x0 = __half2float(g2.x), x1 = __half2float(g2.y);
        float u0 = __half2float(u2.x), u1 = __half2float(u2.y);
        float v0 = (x0 / (1.f + __expf(-x0))) * u0;
        float v1 = (x1 / (1.f + __expf(-x1))) * u1;
        *(__half2*)(gh + (size_t)s * ID + i) = __half2(__float2half(v0), __float2half(v1));
    }
}

// ---------------- final combine (vectorized) -------------------------------------------
__global__ void combine_kernel(const float* __restrict__ res, const h16* __restrict__ ybuf,
                               const int* __restrict__ slot_of, const float* __restrict__ rw,
                               float* __restrict__ out) {
    int t = blockIdx.x;
    int s0 = slot_of[t*4+0], s1 = slot_of[t*4+1], s2 = slot_of[t*4+2], s3 = slot_of[t*4+3];
    float w0 = rw[t*4+0], w1 = rw[t*4+1], w2 = rw[t*4+2], w3 = rw[t*4+3];
    const h16* y0 = ybuf + (size_t)s0 * HDM;
    const h16* y1 = ybuf + (size_t)s1 * HDM;
    const h16* y2 = ybuf + (size_t)s2 * HDM;
    const h16* y3 = ybuf + (size_t)s3 * HDM;
    size_t base = (size_t)t * HDM;
    for (int i = threadIdx.x * 2; i < HDM; i += 512) {
        __half2 a0 = *(const __half2*)(y0 + i);
        __half2 a1 = *(const __half2*)(y1 + i);
        __half2 a2 = *(const __half2*)(y2 + i);
        __half2 a3 = *(const __half2*)(y3 + i);
        float2 rr = *(const float2*)(res + base + i);
        float o0 = rr.x + w0 * __half2float(a0.x) + w1 * __half2float(a1.x)
                        + w2 * __half2float(a2.x) + w3 * __half2float(a3.x);
        float o1 = rr.y + w0 * __half2float(a0.y) + w1 * __half2float(a1.y)
                        + w2 * __half2float(a2.y) + w3 * __half2float(a3.y);
        *(float2*)(out + base + i) = make_float2(o0, o1);
    }
}

// ========================================================================================
extern "C" void kernel_launch(void* const* d_in, const int* in_sizes, int n_in,
                              void* d_out, int out_size) {
    const float* x    = (const float*)d_in[0];
    const float* pe   = (const float*)d_in[1];
    const float* q_w  = (const float*)d_in[3];
    const float* k_w  = (const float*)d_in[4];
    const float* v_w  = (const float*)d_in[5];
    const float* o_w  = (const float*)d_in[6];
    const float* q_nw = (const float*)d_in[7];
    const float* k_nw = (const float*)d_in[8];
    const float* ln1  = (const float*)d_in[9];
    const float* ln2  = (const float*)d_in[10];
    const float* gw   = (const float*)d_in[11];
    const float* gpw  = (const float*)d_in[12];
    const float* upw  = (const float*)d_in[13];
    const float* dpw  = (const float*)d_in[14];
    float* out = (float*)d_out;

    #define SYM(T, p, s) T p; cudaGetSymbolAddress((void**)&p, s)
    SYM(h16*, wqkv_h, g_wqkv_h); SYM(h16*, wqkv_l, g_wqkv_l);
    SYM(h16*, wo_h, g_wo_h);     SYM(h16*, wo_l, g_wo_l);
    SYM(h16*, wgu_h, g_wgu_h);
    SYM(h16*, wd_h, g_wd_h);
    SYM(h16*, xn_h, g_xn_h);     SYM(h16*, xn_l, g_xn_l);
    SYM(float*, qkvlin, g_qkvlin);
    SYM(h16*, qh_h, g_qh_h);     SYM(h16*, qh_l, g_qh_l);
    SYM(h16*, kh_h, g_kh_h);     SYM(h16*, kh_l, g_kh_l);
    SYM(h16*, vt_h, g_vt_h);     SYM(h16*, vt_l, g_vt_l);
    SYM(h16*, ao_h, g_ao_h);     SYM(h16*, ao_l, g_ao_l);
    SYM(float*, res, g_res);
    SYM(float*, h2f, g_h2f);
    SYM(h16*, h2_h, g_h2_h);
    SYM(h16*, gu, g_gu);
    SYM(h16*, gg_h, g_g_h);
    SYM(h16*, ybuf, g_ybuf);
    SYM(int*, tidx, g_tidx);      SYM(float*, trw, g_trw);
    SYM(int*, counts, g_counts);  SYM(int*, offs, g_offs);
    SYM(int*, token_of, g_token_of); SYM(int*, slot_of, g_slot_of);
    #undef SYM

    constexpr int SMEM3 = 2 * (4 * TILE_HALF * 2);   // 81920
    constexpr int SMEM1 = 2 * (2 * TILE_HALF * 2);   // 40960
    static bool attr_done = false;
    static cudaStream_t s2 = nullptr;
    static cudaEvent_t evF = nullptr, evO = nullptr, evJ = nullptr;
    if (!attr_done) {
        cudaFuncSetAttribute(gemm_mma<0,0,3>, cudaFuncAttributeMaxDynamicSharedMemorySize, SMEM3);
        cudaFuncSetAttribute(gemm_mma<2,0,3>, cudaFuncAttributeMaxDynamicSharedMemorySize, SMEM3);
        cudaFuncSetAttribute(gemm_mma<5,1,1>, cudaFuncAttributeMaxDynamicSharedMemorySize, SMEM1);
        cudaFuncSetAttribute(gemm_mma<5,2,1>, cudaFuncAttributeMaxDynamicSharedMemorySize, SMEM1);
        cudaFuncSetAttribute(flash_kernel, cudaFuncAttributeMaxDynamicSharedMemorySize, FSMEM);
        cudaStreamCreateWithFlags(&s2, cudaStreamNonBlocking);
        cudaEventCreateWithFlags(&evF, cudaEventDisableTiming);
        cudaEventCreateWithFlags(&evO, cudaEventDisableTiming);
        cudaEventCreateWithFlags(&evJ, cudaEventDisableTiming);
        attr_done = true;
    }

    const float scale = 0.08838834764831845f;

    // ---- main stream: QKV weight splits + ln1 ----
    size_t nq = (size_t)NH*HD*HDM, nk = (size_t)NKV*HD*HDM;
    split_kernel<<<(unsigned)((nq+4095)/4096), 256>>>(q_w, wqkv_h, wqkv_l, nq);
    split_kernel<<<(unsigned)((nk+4095)/4096), 256>>>(k_w, wqkv_h + nq, wqkv_l + nq, nk);
    split_kernel<<<(unsigned)((nk+4095)/4096), 256>>>(v_w, wqkv_h + nq + nk, wqkv_l + nq + nk, nk);
    rmsnorm_kernel<<<SQ, 256>>>(x, ln1, nullptr, xn_h, xn_l, HDM);
    cudaEventRecord(evF, 0);

    gemm_mma<0,0,3><<<dim3(QKVN/BN, SQ/BM, 1), 256, SMEM3>>>(
        xn_h, xn_l, HDM, 0, wqkv_h, wqkv_l, HDM, 0,
        qkvlin, nullptr, QKVN, 0, HDM, WSCI, nullptr, 0, nullptr, nullptr, nullptr);

    // ---- side stream: O-proj split + MoE weight splits ----
    cudaStreamWaitEvent(s2, evF, 0);
    size_t no = (size_t)HDM*NH*HD;
    split_kernel<<<(unsigned)((no+4095)/4096), 256, 0, s2>>>(o_w, wo_h, wo_l, no);
    cudaEventRecord(evO, s2);
    size_t ngu = (size_t)NE*ID*HDM;
    split_gu_kernel<<<(unsigned)((ngu+4095)/4096), 256, 0, s2>>>(gpw, upw, wgu_h);
    size_t nd = (size_t)NE*HDM*ID;
    split_kernel<<<(unsigned)((nd+4095)/4096), 256, 0, s2>>>(dpw, wd_h, nullptr, nd);
    cudaEventRecord(evJ, s2);

    norm_rope_kernel<<<dim3(SQ, NH + NKV), HD>>>(qkvlin, q_nw, k_nw, pe,
                                                 qh_h, qh_l, kh_h, kh_l);
    vtrans_kernel<<<dim3(SQ/32, HD/32, NKV), dim3(32, 8)>>>(qkvlin, vt_h, vt_l);
    flash_kernel<<<dim3(SQ/128, NH), 256, FSMEM>>>(
        qh_h, qh_l, kh_h, kh_l, vt_h, vt_l, ao_h, ao_l, scale);
    cudaStreamWaitEvent(0, evO, 0);
    gemm_mma<2,0,3><<<dim3(HDM/BN, SQ/BM, 1), 256, SMEM3>>>(
        ao_h, ao_l, NH*HD, 0, wo_h, wo_l, NH*HD, 0,
        res, nullptr, HDM, 0, NH*HD, WSCI, x, HDM, nullptr, nullptr, nullptr);

    // ---- MoE ----
    rmsnorm_kernel<<<SQ, 256>>>(res, ln2, h2f, h2_h, nullptr, HDM);
    gate_topk_kernel<<<SQ, 256>>>(h2f, gw, tidx, trw);
    route_kernel<<<1, 32>>>(tidx, counts, offs, token_of, slot_of);
    cudaStreamWaitEvent(0, evJ, 0);
    gemm_mma<5,1,1><<<dim3(GUN/BN, NSLOT/BM, NE), 256, SMEM1>>>(
        h2_h, nullptr, HDM, 0, wgu_h, nullptr, HDM, (long)GUN*HDM,
        nullptr, gu, GUN, 0, HDM, WSCI, nullptr, 0, counts, offs, token_of);
    silu_mul_kernel<<<NSLOT, 256>>>(gu, gg_h);
    gemm_mma<5,2,1><<<dim3(HDM/BN, NSLOT/BM, NE), 256, SMEM1>>>(
        gg_h, nullptr, ID, 0, wd_h, nullptr, ID, (long)HDM*ID,
        nullptr, ybuf, HDM, 0, ID, WSCI, nullptr, 0, counts, offs, token_of);
    combine_kernel<<<SQ, 256>>>(res, ybuf, slot_of, trw, out);
}

// round 16
// speedup vs baseline: 1.0792x; 1.0792x over previous
#include <cuda_runtime.h>
#include <cuda_fp16.h>
#include <cstdint>

#define SQ    2048
#define HDM   2048
#define NH    32
#define NKV   4
#define HD    128
#define NE    16
#define ID    768
#define TOPK  4
#define NSLOT (SQ*TOPK)
#define QKVN  (NH*HD + 2*NKV*HD)   // 5120
#define GUN   (2*ID)               // 1536
#define WSC   64.0f
#define WSCI  (1.0f/64.0f)

typedef __half h16;

// ---------------- device scratch -------------------------------------------
__device__ __align__(16) h16 g_wqkv_h[(size_t)QKVN*HDM],  g_wqkv_l[(size_t)QKVN*HDM];
__device__ __align__(16) h16 g_wo_h[(size_t)HDM*NH*HD],   g_wo_l[(size_t)HDM*NH*HD];
__device__ __align__(16) h16 g_wgu_h[(size_t)NE*GUN*HDM];
__device__ __align__(16) h16 g_wd_h[(size_t)NE*HDM*ID];
__device__ __align__(16) h16 g_xn_h[(size_t)SQ*HDM],      g_xn_l[(size_t)SQ*HDM];
__device__ __align__(16) float g_qkvlin[(size_t)SQ*QKVN];
__device__ __align__(16) h16 g_qh_h[(size_t)NH*SQ*HD],    g_qh_l[(size_t)NH*SQ*HD];
__device__ __align__(16) h16 g_kh_h[(size_t)NKV*SQ*HD],   g_kh_l[(size_t)NKV*SQ*HD];
__device__ __align__(16) h16 g_vt_h[(size_t)NKV*HD*SQ];
__device__ __align__(16) h16 g_ao_h[(size_t)SQ*NH*HD],    g_ao_l[(size_t)SQ*NH*HD];
__device__ __align__(16) float g_res[SQ*HDM];
__device__ __align__(16) float g_h2f[SQ*HDM];
__device__ __align__(16) h16 g_h2_h[(size_t)SQ*HDM];
__device__ __align__(16) h16 g_gu[(size_t)NSLOT*GUN];
__device__ __align__(16) h16 g_g_h[(size_t)NSLOT*ID];
__device__ __align__(16) h16 g_ybuf[(size_t)NSLOT*HDM];
__device__ int   g_tidx[NSLOT];
__device__ float g_trw[NSLOT];
__device__ int   g_counts[NE];
__device__ int   g_offs[NE];
__device__ int   g_token_of[NSLOT];
__device__ int   g_slot_of[NSLOT];

// ---------------- helpers ----------------------------------------------------
__device__ __forceinline__ void splitf(float v, h16& h, h16& l) {
    h = __float2half(v);
    l = __float2half(v - __half2float(h));
}
__device__ __forceinline__ uint32_t pack2h(h16 a, h16 b) {
    __half2 t(a, b);
    return *(uint32_t*)&t;
}
__device__ __forceinline__ void ldsm4(uint32_t r[4], uint32_t addr) {
    asm volatile("ldmatrix.sync.aligned.m8n8.x4.shared.b16 {%0,%1,%2,%3},[%4];"
        : "=r"(r[0]), "=r"(r[1]), "=r"(r[2]), "=r"(r[3]) : "r"(addr));
}
__device__ __forceinline__ void mma16816(float c[4], const uint32_t a[4], const uint32_t b[2]) {
    asm volatile("mma.sync.aligned.m16n8k16.row.col.f32.f16.f16.f32 "
        "{%0,%1,%2,%3},{%4,%5,%6,%7},{%8,%9},{%0,%1,%2,%3};"
        : "+f"(c[0]), "+f"(c[1]), "+f"(c[2]), "+f"(c[3])
        : "r"(a[0]), "r"(a[1]), "r"(a[2]), "r"(a[3]), "r"(b[0]), "r"(b[1]));
}
__device__ __forceinline__ void cp16(uint32_t dst, const void* src, int sz) {
    asm volatile("cp.async.cg.shared.global [%0],[%1],16,%2;\n" :: "r"(dst), "l"(src), "r"(sz));
}
__device__ __forceinline__ void cp_commit() { asm volatile("cp.async.commit_group;\n"); }
__device__ __forceinline__ void cp_wait1() { asm volatile("cp.async.wait_group 1;\n"); }

__device__ __forceinline__ float blockReduceSum(float v) {
    __shared__ float sh[8];
    int lane = threadIdx.x & 31, w = threadIdx.x >> 5;
    #pragma unroll
    for (int o = 16; o; o >>= 1) v += __shfl_xor_sync(0xffffffffu, v, o);
    if (lane == 0) sh[w] = v;
    __syncthreads();
    float r = (threadIdx.x < (blockDim.x >> 5)) ? sh[threadIdx.x] : 0.f;
    if (w == 0) {
        #pragma unroll
        for (int o = 4; o; o >>= 1) r += __shfl_xor_sync(0xffffffffu, r, o);
        if (lane == 0) sh[0] = r;
    }
    __syncthreads();
    r = sh[0];
    __syncthreads();
    return r;
}

// ---------------- weight split conversions (weights pre-scaled by WSC) ----------
__global__ void split_kernel(const float* __restrict__ in, h16* __restrict__ hi,
                             h16* __restrict__ lo, size_t n) {
    size_t base = (size_t)blockIdx.x * 4096 + threadIdx.x * 4;
    #pragma unroll
    for (int u = 0; u < 4; u++) {
        size_t i = base + u * 1024;
        if (i >= n) return;
        float4 v = *(const float4*)(in + i);
        h16 h0, l0, h1, l1, h2, l2, h3, l3;
        splitf(v.x * WSC, h0, l0); splitf(v.y * WSC, h1, l1);
        splitf(v.z * WSC, h2, l2); splitf(v.w * WSC, h3, l3);
        *(__half2*)(hi + i)     = __half2(h0, h1);
        *(__half2*)(hi + i + 2) = __half2(h2, h3);
        if (lo) {
            *(__half2*)(lo + i)     = __half2(l0, l1);
            *(__half2*)(lo + i + 2) = __half2(l2, l3);
        }
    }
}

__global__ void split_gu_kernel(const float* __restrict__ gp, const float* __restrict__ up,
                                h16* __restrict__ hi) {
    size_t base = (size_t)blockIdx.x * 4096 + threadIdx.x * 4;
    #pragma unroll
    for (int u = 0; u < 4; u++) {
        size_t i = base + u * 1024;
        if (i >= (size_t)NE * ID * HDM) return;
        size_t e = i / ((size_t)ID * HDM);
        size_t rem = i - e * (size_t)ID * HDM;
        size_t dg = e * (size_t)GUN * HDM + rem;
        size_t du = dg + (size_t)ID * HDM;
        float4 vg = *(const float4*)(gp + i);
        float4 vu = *(const float4*)(up + i);
        *(__half2*)(hi + dg)     = __half2(__float2half(vg.x * WSC), __float2half(vg.y * WSC));
        *(__half2*)(hi + dg + 2) = __half2(__float2half(vg.z * WSC), __float2half(vg.w * WSC));
        *(__half2*)(hi + du)     = __half2(__float2half(vu.x * WSC), __float2half(vu.y * WSC));
        *(__half2*)(hi + du + 2) = __half2(__float2half(vu.z * WSC), __float2half(vu.w * WSC));
    }
}

// ---------------- rms norm (vectorized, ncols fixed at 2048, 256 thr) ------------
__global__ void rmsnorm_kernel(const float* __restrict__ x, const float* __restrict__ w,
                               float* __restrict__ outf, h16* __restrict__ oh,
                               h16* __restrict__ ol, int ncols) {
    size_t base = (size_t)blockIdx.x * 2048;
    int i0 = threadIdx.x * 4;
    float4 a = *(const float4*)(x + base + i0);
    float4 b = *(const float4*)(x + base + i0 + 1024);
    float ss = a.x*a.x + a.y*a.y + a.z*a.z + a.w*a.w
             + b.x*b.x + b.y*b.y + b.z*b.z + b.w*b.w;
    ss = blockReduceSum(ss);
    float r = rsqrtf(ss * (1.f / 2048.f) + 1e-6f);
    float4 wa = *(const float4*)(w + i0);
    float4 wb = *(const float4*)(w + i0 + 1024);
    float va[8] = {wa.x*a.x*r, wa.y*a.y*r, wa.z*a.z*r, wa.w*a.w*r,
                   wb.x*b.x*r, wb.y*b.y*r, wb.z*b.z*r, wb.w*b.w*r};
    if (outf) {
        *(float4*)(outf + base + i0)        = make_float4(va[0], va[1], va[2], va[3]);
        *(float4*)(outf + base + i0 + 1024) = make_float4(va[4], va[5], va[6], va[7]);
    }
    if (oh) {
        h16 h[8], l[8];
        #pragma unroll
        for (int k = 0; k < 8; k++) splitf(va[k], h[k], l[k]);
        *(__half2*)(oh + base + i0)            = __half2(h[0], h[1]);
        *(__half2*)(oh + base + i0 + 2)        = __half2(h[2], h[3]);
        *(__half2*)(oh + base + i0 + 1024)     = __half2(h[4], h[5]);
        *(__half2*)(oh + base + i0 + 1026)     = __half2(h[6], h[7]);
        if (ol) {
            *(__half2*)(ol + base + i0)        = __half2(l[0], l[1]);
            *(__half2*)(ol + base + i0 + 2)    = __half2(l[2], l[3]);
            *(__half2*)(ol + base + i0 + 1024) = __half2(l[4], l[5]);
            *(__half2*)(ol + base + i0 + 1026) = __half2(l[6], l[7]);
        }
    }
}

// ---------------- per-head rmsnorm + rope (Q and K fused in one grid) --------------
__global__ void norm_rope_kernel(const float* __restrict__ lin,
                                 const float* __restrict__ qnw, const float* __restrict__ knw,
                                 const float* __restrict__ pe,
                                 h16* __restrict__ qh, h16* __restrict__ ql,
                                 h16* __restrict__ kh, h16* __restrict__ kl) {
    int t = blockIdx.x, hh = blockIdx.y, d = threadIdx.x;
    bool isq = hh < NH;
    int colbase = isq ? hh * HD : (NH * HD + (hh - NH) * HD);
    const float* nw = isq ? qnw : knw;
    float v = lin[(size_t)t * QKVN + colbase + d];
    float ss = v * v;
    #pragma unroll
    for (int o = 16; o; o >>= 1) ss += __shfl_xor_sync(0xffffffffu, ss, o);
    __shared__ float wsum[4];
    if ((d & 31) == 0) wsum[d >> 5] = ss;
    __syncthreads();
    float tot = wsum[0] + wsum[1] + wsum[2] + wsum[3];
    float xn = nw[d] * v * rsqrtf(tot * (1.f / HD) + 1e-6f);
    __shared__ float sh[HD];
    sh[d] = xn;
    __syncthreads();
    float c = pe[(size_t)t * HD + d];
    float s = pe[(size_t)SQ * HD + (size_t)t * HD + d];
    float rot = (d < HD / 2) ? -sh[d + HD / 2] : sh[d - HD / 2];
    float o = xn * c + rot * s;
    h16 ho, lo; splitf(o, ho, lo);
    if (isq) {
        size_t idx = ((size_t)hh * SQ + t) * HD + d;
        qh[idx] = ho; ql[idx] = lo;
    } else {
        size_t idx = ((size_t)(hh - NH) * SQ + t) * HD + d;
        kh[idx] = ho; kl[idx] = lo;
    }
}

// ---------------- V transpose (fp16 single stream), coalesced via smem tile ------
__global__ void vtrans_kernel(const float* __restrict__ qkvlin, h16* __restrict__ vh) {
    __shared__ float tile[32][33];
    int kv = blockIdx.z;
    int t0 = blockIdx.x * 32, d0 = blockIdx.y * 32;
    int tx = threadIdx.x, ty = threadIdx.y;
    #pragma unroll
    for (int i = ty; i < 32; i += 8)
        tile[i][tx] = qkvlin[(size_t)(t0 + i) * QKVN + (NH * HD + NKV * HD) + kv * HD + d0 + tx];
    __syncthreads();
    #pragma unroll
    for (int i = ty; i < 32; i += 8) {
        size_t idx = ((size_t)kv * HD + d0 + i) * SQ + t0 + tx;
        vh[idx] = __float2half(tile[tx][i]);
    }
}

// =================================================================================
// fp16 mma.sync GEMM, 2-stage cp.async, 2 CTAs/SM (R13 binding config).
// NS=3 (hi/lo x3 split) or NS=1 (single stream).
// MODE 0 dense / 1 gather rows / 2 direct ragged rows
// EPI 0 fp32*cscale / 2 fp32*cscale+residual / 5 fp16*cscale
// =================================================================================
#define BM 128
#define BN 128
#define BK 32
#define BKP 40
#define TILE_HALF (BM * BKP)

template<int EPI, int MODE, int NS>
__global__ void __launch_bounds__(256, 2) gemm_mma(
    const h16* __restrict__ Ah, const h16* __restrict__ Al, int lda, long sAz,
    const h16* __restrict__ Bh, const h16* __restrict__ Bl, int ldb, long sBz,
    float* __restrict__ Cf, h16* __restrict__ Chf, int ldc, long sCz,
    int K, float cscale, const float* __restrict__ epi, int lde,
    const int* __restrict__ counts, const int* __restrict__ offs,
    const int* __restrict__ token_of)
{
    constexpr uint32_t STB = (uint32_t)((NS == 3 ? 4 : 2) * TILE_HALF * 2);
    constexpr uint32_t OFF_AL = TILE_HALF * 2;
    constexpr uint32_t OFF_BH = (NS == 3 ? 2 : 1) * TILE_HALF * 2;
    constexpr uint32_t OFF_BL = 3 * TILE_HALF * 2;

    int z = blockIdx.z;
    int m0 = blockIdx.y * BM, n0 = blockIdx.x * BN;
    int Me = 0x7fffffff, off = 0;
    if (MODE != 0) { Me = counts[z]; if (m0 >= Me) return; off = offs[z]; }
    int nkt = K / BK;

    const h16* Ahp = Ah; const h16* Alp = Al;
    if (MODE == 0) { Ahp += (size_t)z * sAz; if (NS == 3) Alp += (size_t)z * sAz; }
    const h16* Bhp = Bh + (size_t)z * sBz;
    const h16* Blp = (NS == 3) ? (Bl + (size_t)z * sBz) : nullptr;

    extern __shared__ h16 smem[];
    uint32_t sbase = (uint32_t)__cvta_generic_to_shared(smem);

    int tid = threadIdx.x;
    int lr = tid >> 2;
    int lc = (tid & 3) * 8;

    int rl0 = m0 + lr, rl1 = m0 + lr + 64;
    bool av0 = true, av1 = true;
    size_t ar0, ar1;
    if (MODE == 1) {
        av0 = rl0 < Me; av1 = rl1 < Me;
        ar0 = av0 ? (size_t)token_of[off + rl0] : 0;
        ar1 = av1 ? (size_t)token_of[off + rl1] : 0;
    } else if (MODE == 2) {
        av0 = rl0 < Me; av1 = rl1 < Me;
        ar0 = av0 ? (size_t)(off + rl0) : 0;
        ar1 = av1 ? (size_t)(off + rl1) : 0;
    } else { ar0 = rl0; ar1 = rl1; }
    size_t offA0 = ar0 * (size_t)lda + lc;
    size_t offA1 = ar1 * (size_t)lda + lc;
    size_t offB0 = (size_t)(n0 + lr) * ldb + lc;
    size_t offB1 = (size_t)(n0 + lr + 64) * ldb + lc;
    int sz0 = av0 ? 16 : 0, sz1 = av1 ? 16 : 0;

    uint32_t dA0 = sbase + (lr * BKP + lc) * 2;
    uint32_t dA1 = sbase + ((lr + 64) * BKP + lc) * 2;

    const int warp = tid >> 5, lane = tid & 31;
    const int wm = (warp >> 1) * 32;
    const int wn = (warp & 1) * 64;
    const int ldr = lane & 15;
    const int ldc8 = (lane >> 4) * 8;

    float acc[2][8][4];
    #pragma unroll
    for (int i = 0; i < 2; i++)
        #pragma unroll
        for (int j = 0; j < 8; j++)
            #pragma unroll
            for (int q = 0; q < 4; q++) acc[i][j][q] = 0.f;

    #define LOAD_STAGE(kt) do {                                          \
        uint32_t nb = (uint32_t)((kt) & 1) * STB;                         \
        int k0_ = (kt) * BK;                                              \
        cp16(dA0 + nb, Ahp + offA0 + k0_, sz0);                           \
        cp16(dA1 + nb, Ahp + offA1 + k0_, sz1);                           \
        cp16(dA0 + nb + OFF_BH, Bhp + offB0 + k0_, 16);                   \
        cp16(dA1 + nb + OFF_BH, Bhp + offB1 + k0_, 16);                   \
        if (NS == 3) {                                                    \
            cp16(dA0 + nb + OFF_AL, Alp + offA0 + k0_, sz0);              \
            cp16(dA1 + nb + OFF_AL, Alp + offA1 + k0_, sz1);              \
            cp16(dA0 + nb + OFF_BL, Blp + offB0 + k0_, 16);               \
            cp16(dA1 + nb + OFF_BL, Blp + offB1 + k0_, 16);               \
        }                                                                 \
    } while (0)

    LOAD_STAGE(0);
    cp_commit();

    for (int kt = 0; kt < nkt; kt++) {
        if (kt + 1 < nkt) LOAD_STAGE(kt + 1);
        cp_commit();
        cp_wait1();
        __syncthreads();

        uint32_t bA = sbase + (uint32_t)(kt & 1) * STB;
        #pragma unroll
        for (int ks = 0; ks < 2; ks++) {
            int kk = ks * 16 + ldc8;
            uint32_t ah[2][4], al[2][4], bh[8][2], bl[8][2];
            #pragma unroll
            for (int mt = 0; mt < 2; mt++) {
                uint32_t adr = ((wm + mt * 16 + ldr) * BKP + kk) * 2;
                ldsm4(ah[mt], bA + adr);
                if (NS == 3) ldsm4(al[mt], bA + OFF_AL + adr);
            }
            #pragma unroll
            for (int np = 0; np < 4; np++) {
                uint32_t adr = ((wn + np * 16 + ldr) * BKP + kk) * 2;
                uint32_t r[4];
                ldsm4(r, bA + OFF_BH + adr);
                bh[np*2][0] = r[0]; bh[np*2+1][0] = r[1]; bh[np*2][1] = r[2]; bh[np*2+1][1] = r[3];
                if (NS == 3) {
                    ldsm4(r, bA + OFF_BL + adr);
                    bl[np*2][0] = r[0]; bl[np*2+1][0] = r[1]; bl[np*2][1] = r[2]; bl[np*2+1][1] = r[3];
                }
            }
            #pragma unroll
            for (int mt = 0; mt < 2; mt++)
                #pragma unroll
                for (int nt = 0; nt < 8; nt++) {
                    mma16816(acc[mt][nt], ah[mt], bh[nt]);
                    if (NS == 3) {
                        mma16816(acc[mt][nt], ah[mt], bl[nt]);
                        mma16816(acc[mt][nt], al[mt], bh[nt]);
                    }
                }
        }
        __syncthreads();
    }
    #undef LOAD_STAGE

    int er = lane >> 2;
    int ec = (lane & 3) * 2;
    #pragma unroll
    for (int mt = 0; mt < 2; mt++) {
        #pragma unroll
        for (int h = 0; h < 2; h++) {
            int mloc = m0 + wm + mt * 16 + h * 8 + er;
            bool mvalid = (MODE == 0) || (mloc < Me);
            if (!mvalid) continue;
            size_t crow = (MODE == 0) ? (size_t)mloc : (size_t)(off + mloc);
            #pragma unroll
            for (int nt = 0; nt < 8; nt++) {
                int col = n0 + wn + nt * 8 + ec;
                float v0 = acc[mt][nt][h * 2 + 0] * cscale;
                float v1 = acc[mt][nt][h * 2 + 1] * cscale;
                size_t ci = (size_t)z * sCz + crow * ldc + col;
                if (EPI == 5) {
                    *(__half2*)(Chf + ci) = __half2(__float2half(v0), __float2half(v1));
                } else {
                    if (EPI == 2) {
                        float2 rr = *(const float2*)(epi + (size_t)mloc * lde + col);
                        v0 += rr.x; v1 += rr.y;
                    }
                    *(float2*)(Cf + ci) = make_float2(v0, v1);
                }
            }
        }
    }
}

// =================================================================================
// Fused flash attention: QK x3 (Q hi/lo, K hi/lo), PV x1 (P fp16, V fp16).
// Reversed m-block order.
// smem: QH 0 | QL 17408 | K stages 2x17408 @34816 | V stages 2x9216 @69632
// =================================================================================
#define FQH 0
#define FQL 17408
#define FKOFF 34816
#define FVOFF 69632
#define FSMEM ((69632 + 2 * 9216) * 2)   /* 176128 B */

__global__ void __launch_bounds__(256, 1) flash_kernel(
    const h16* __restrict__ qh_h, const h16* __restrict__ qh_l,
    const h16* __restrict__ kh_h, const h16* __restrict__ kh_l,
    const h16* __restrict__ vt_h,
    h16* __restrict__ ao_h, h16* __restrict__ ao_l, float scale)
{
    int m0 = (gridDim.x - 1 - blockIdx.x) * 128;
    int h = blockIdx.y;
    int kvh = h >> 3;

    extern __shared__ h16 fsm[];
    uint32_t sb = (uint32_t)__cvta_generic_to_shared(fsm);

    int tid = threadIdx.x, wid = tid >> 5, lane = tid & 31;
    const int ldr = lane & 15, ldc8 = (lane >> 4) * 8;

    {
        const h16* qs_h = qh_h + ((size_t)h * SQ + m0) * HD;
        const h16* qs_l = qh_l + ((size_t)h * SQ + m0) * HD;
        for (int c = tid; c < 2048; c += 256) {
            int r = c >> 4, col = (c & 15) * 8;
            size_t go = (size_t)r * HD + col;
            cp16(sb + (uint32_t)(FQH + r * 136 + col) * 2, qs_h + go, 16);
            cp16(sb + (uint32_t)(FQL + r * 136 + col) * 2, qs_l + go, 16);
        }
    }
    cp_commit();

    int nj = (m0 + 128) >> 6;

    #define LOAD_KV(jj, stg) do {                                                     \
        for (int c = tid; c < 1024; c += 256) {                                        \
            int kr = c >> 4, kc = (c & 15) * 8;                                        \
            size_t kgo = ((size_t)kvh * SQ + (jj) * 64 + kr) * HD + kc;                \
            uint32_t kd = sb + (uint32_t)(FKOFF + (stg) * 17408 + kr * 136 + kc) * 2;  \
            cp16(kd, kh_h + kgo, 16);                                                  \
            cp16(kd + 8704 * 2, kh_l + kgo, 16);                                       \
            int vr = c >> 3, vc = (c & 7) * 8;                                         \
            size_t vgo = ((size_t)kvh * HD + vr) * SQ + (jj) * 64 + vc;                \
            cp16(sb + (uint32_t)(FVOFF + (stg) * 9216 + vr * 72 + vc) * 2, vt_h + vgo, 16); \
        }                                                                               \
    } while (0)

    LOAD_KV(0, 0);
    cp_commit();

    int rbase = wid * 16;
    float m_r0 = -1e30f, m_r1 = -1e30f, l_r0 = 0.f, l_r1 = 0.f;
    float o[16][4];
    #pragma unroll
    for (int i = 0; i < 16; i++)
        #pragma unroll
        for (int q = 0; q < 4; q++) o[i][q] = 0.f;

    int grow0 = m0 + rbase + (lane >> 2);
    int ar = rbase + ldr;

    for (int j = 0; j < nj; j++) {
        if (j + 1 < nj) LOAD_KV(j + 1, (j + 1) & 1);
        cp_commit();
        cp_wait1();
        __syncthreads();

        bool skip = (j * 64 > m0 + rbase + 15);
        if (!skip) {
            int st = j & 1;
            uint32_t kst = (uint32_t)(FKOFF + st * 17408);
            uint32_t vst = (uint32_t)(FVOFF + st * 9216);

            float s[8][4];
            #pragma unroll
            for (int nt = 0; nt < 8; nt++)
                #pragma unroll
                for (int q = 0; q < 4; q++) s[nt][q] = 0.f;

            // ---- S = Q K^T : x3 (qh*kh + qh*kl + ql*kh) ----
            #pragma unroll
            for (int kt = 0; kt < 8; kt++) {
                int kk = kt * 16 + ldc8;
                uint32_t aqh[4], aql[4];
                ldsm4(aqh, sb + (uint32_t)(FQH + ar * 136 + kk) * 2);
                ldsm4(aql, sb + (uint32_t)(FQL + ar * 136 + kk) * 2);
                #pragma unroll
                for (int np = 0; np < 4; np++) {
                    uint32_t kadr = sb + (kst + (np * 16 + ldr) * 136 + kk) * 2;
                    uint32_t rh[4], rl[4];
                    ldsm4(rh, kadr);
                    ldsm4(rl, kadr + 8704 * 2);
                    uint32_t b0h[2] = {rh[0], rh[2]}, b1h[2] = {rh[1], rh[3]};
                    uint32_t b0l[2] = {rl[0], rl[2]}, b1l[2] = {rl[1], rl[3]};
                    mma16816(s[np*2],   aqh, b0h);
                    mma16816(s[np*2],   aqh, b0l);
                    mma16816(s[np*2],   aql, b0h);
                    mma16816(s[np*2+1], aqh, b1h);
                    mma16816(s[np*2+1], aqh, b1l);
                    mma16816(s[np*2+1], aql, b1h);
                }
            }

            float mx0 = -1e30f, mx1 = -1e30f;
            #pragma unroll
            for (int nt = 0; nt < 8; nt++) {
                int gc = j * 64 + nt * 8 + (lane & 3) * 2;
                float v0 = s[nt][0] * scale; if (gc     > grow0)     v0 = -1e30f;
                float v1 = s[nt][1] * scale; if (gc + 1 > grow0)     v1 = -1e30f;
                float v2 = s[nt][2] * scale; if (gc     > grow0 + 8) v2 = -1e30f;
                float v3 = s[nt][3] * scale; if (gc + 1 > grow0 + 8) v3 = -1e30f;
                s[nt][0] = v0; s[nt][1] = v1; s[nt][2] = v2; s[nt][3] = v3;
                mx0 = fmaxf(mx0, fmaxf(v0, v1));
                mx1 = fmaxf(mx1, fmaxf(v2, v3));
            }
            mx0 = fmaxf(mx0, __shfl_xor_sync(0xffffffffu, mx0, 1));
            mx0 = fmaxf(mx0, __shfl_xor_sync(0xffffffffu, mx0, 2));
            mx1 = fmaxf(mx1, __shfl_xor_sync(0xffffffffu, mx1, 1));
            mx1 = fmaxf(mx1, __shfl_xor_sync(0xffffffffu, mx1, 2));
            float mn0 = fmaxf(m_r0, mx0), mn1 = fmaxf(m_r1, mx1);
            float al0 = __expf(m_r0 - mn0), al1 = __expf(m_r1 - mn1);
            float sm0 = 0.f, sm1 = 0.f;
            #pragma unroll
            for (int nt = 0; nt < 8; nt++) {
                float p0 = __expf(s[nt][0] - mn0);
                float p1 = __expf(s[nt][1] - mn0);
                float p2 = __expf(s[nt][2] - mn1);
                float p3 = __expf(s[nt][3] - mn1);
                s[nt][0] = p0; s[nt][1] = p1; s[nt][2] = p2; s[nt][3] = p3;
                sm0 += p0 + p1; sm1 += p2 + p3;
            }
            sm0 += __shfl_xor_sync(0xffffffffu, sm0, 1);
            sm0 += __shfl_xor_sync(0xffffffffu, sm0, 2);
            sm1 += __shfl_xor_sync(0xffffffffu, sm1, 1);
            sm1 += __shfl_xor_sync(0xffffffffu, sm1, 2);
            l_r0 = l_r0 * al0 + sm0;
            l_r1 = l_r1 * al1 + sm1;
            m_r0 = mn0; m_r1 = mn1;
            #pragma unroll
            for (int i = 0; i < 16; i++) {
                o[i][0] *= al0; o[i][1] *= al0;
                o[i][2] *= al1; o[i][3] *= al1;
            }

            // ---- O += P V : x1 (P fp16, V fp16) ----
            #pragma unroll
            for (int kt2 = 0; kt2 < 4; kt2++) {
                uint32_t ah[4];
                ah[0] = pack2h(__float2half(s[2*kt2][0]),   __float2half(s[2*kt2][1]));
                ah[1] = pack2h(__float2half(s[2*kt2][2]),   __float2half(s[2*kt2][3]));
                ah[2] = pack2h(__float2half(s[2*kt2+1][0]), __float2half(s[2*kt2+1][1]));
                ah[3] = pack2h(__float2half(s[2*kt2+1][2]), __float2half(s[2*kt2+1][3]));
                int kk2 = kt2 * 16 + ldc8;
                #pragma unroll
                for (int np = 0; np < 8; np++) {
                    uint32_t vadr = sb + (vst + (np * 16 + ldr) * 72 + kk2) * 2;
                    uint32_t rh[4];
                    ldsm4(rh, vadr);
                    uint32_t b0h[2] = {rh[0], rh[2]}, b1h[2] = {rh[1], rh[3]};
                    mma16816(o[np*2],   ah, b0h);
                    mma16816(o[np*2+1], ah, b1h);
                }
            }
        }
        __syncthreads();
    }
    #undef LOAD_KV

    float inv0 = 1.f / l_r0, inv1 = 1.f / l_r1;
    int row0 = m0 + rbase + (lane >> 2);
    size_t base0 = (size_t)row0 * (NH * HD) + (size_t)h * HD;
    size_t base1 = base0 + (size_t)8 * (NH * HD);
    #pragma unroll
    for (int nt = 0; nt < 16; nt++) {
        int col = nt * 8 + (lane & 3) * 2;
        h16 h0, lo0, h1, lo1;
        splitf(o[nt][0] * inv0, h0, lo0); splitf(o[nt][1] * inv0, h1, lo1);
        *(__half2*)(ao_h + base0 + col) = __half2(h0, h1);
        *(__half2*)(ao_l + base0 + col) = __half2(lo0, lo1);
        splitf(o[nt][2] * inv1, h0, lo0); splitf(o[nt][3] * inv1, h1, lo1);
        *(__half2*)(ao_h + base1 + col) = __half2(h0, h1);
        *(__half2*)(ao_l + base1 + col) = __half2(lo0, lo1);
    }
}

// ---------------- router (smem-staged row, vectorized load) -------------------------
__global__ void gate_topk_kernel(const float* __restrict__ h2, const float* __restrict__ gw,
                                 int* __restrict__ oidx, float* __restrict__ orw) {
    int t = blockIdx.x;
    __shared__ float srow[HDM];
    const float* hr = h2 + (size_t)t * HDM;
    {
        int i0 = threadIdx.x * 4;
        *(float4*)(srow + i0)        = *(const float4*)(hr + i0);
        *(float4*)(srow + i0 + 1024) = *(const float4*)(hr + i0 + 1024);
    }
    __syncthreads();

    int e = threadIdx.x >> 4, l = threadIdx.x & 15;
    const float* wr = gw + (size_t)e * HDM;
    float p = 0.f;
    for (int k = l; k < HDM; k += 16) p += srow[k] * wr[k];
    #pragma unroll
    for (int o = 8; o; o >>= 1) p += __shfl_xor_sync(0xffffffffu, p, o);
    __shared__ float slog[NE];
    if (l == 0) slog[e] = p;
    __syncthreads();
    if (threadIdx.x == 0) {
        float pr[NE];
        float mx = -3.4e38f;
        for (int i = 0; i < NE; i++) { pr[i] = slog[i]; mx = fmaxf(mx, pr[i]); }
        float sum = 0.f;
        for (int i = 0; i < NE; i++) { pr[i] = __expf(pr[i] - mx); sum += pr[i]; }
        float inv = 1.f / sum;
        for (int i = 0; i < NE; i++) pr[i] *= inv;
        int sel[TOPK]; float sv[TOPK]; float wsum = 0.f;
        for (int k = 0; k < TOPK; k++) {
            int best = 0; float bv = -1.f;
            for (int i = 0; i < NE; i++)
                if (pr[i] > bv) { bv = pr[i]; best = i; }
            sel[k] = best; sv[k] = bv; wsum += bv; pr[best] = -2.f;
        }
        float winv = 1.f / wsum;
        for (int k = 0; k < TOPK; k++) { oidx[t * TOPK + k] = sel[k]; orw[t * TOPK + k] = sv[k] * winv; }
    }
}

// ---------------- deterministic routing sort ----------------------------------------
__global__ void route_kernel(const int* __restrict__ idx, int* __restrict__ counts,
                             int* __restrict__ offs, int* __restrict__ token_of,
                             int* __restrict__ slot_of) {
    int c = threadIdx.x;
    int start = c * (NSLOT / 32);
    int cnt[NE];
    #pragma unroll
    for (int e = 0; e < NE; e++) cnt[e] = 0;
    for (int i = 0; i < NSLOT / 32; i++) cnt[idx[start + i]]++;
    __shared__ int scnt[32][NE];
    __shared__ int sbase[32][NE];
    for (int e = 0; e < NE; e++) scnt[c][e] = cnt[e];
    __syncthreads();
    if (c == 0) {
        int off = 0;
        for (int e = 0; e < NE; e++) {
            offs[e] = off;
            int run = off;
            for (int cc = 0; cc < 32; cc++) { sbase[cc][e] = run; run += scnt[cc][e]; }
            counts[e] = run - off;
            off = run;
        }
    }
    __syncthreads();
    int base[NE];
    #pragma unroll
    for (int e = 0; e < NE; e++) base[e] = sbase[c][e];
    for (int i = 0; i < NSLOT / 32; i++) {
        int entry = start + i;
        int e = idx[entry];
        int pos = base[e]++;
        token_of[pos] = entry >> 2;
        slot_of[entry] = pos;
    }
}

// ---------------- silu(g)*u (fp16 in/out, vectorized) ---------------------------------
__global__ void silu_mul_kernel(const h16* __restrict__ gu, h16* __restrict__ gh) {
    int s = blockIdx.x;
    const h16* row = gu + (size_t)s * GUN;
    for (int i = threadIdx.x * 2; i < ID; i += 512) {
        __half2 g2 = *(const __half2*)(row + i);
        __half2 u2 = *(const __half2*)(row + ID + i);
        float x0 = __half2float(g2.x), x1 = __half2float(g2.y);
        float u0 = __half2float(u2.x), u1 = __half2float(u2.y);
        float v0 = (x0 / (1.f + __expf(-x0))) * u0;
        float v1 = (x1 / (1.f + __expf(-x1))) * u1;
        *(__half2*)(gh + (size_t)s * ID + i) = __half2(__float2half(v0), __float2half(v1));
    }
}

// ---------------- final combine (vectorized) -------------------------------------------
__global__ void combine_kernel(const float* __restrict__ res, const h16* __restrict__ ybuf,
                               const int* __restrict__ slot_of, const float* __restrict__ rw,
                               float* __restrict__ out) {
    int t = blockIdx.x;
    int s0 = slot_of[t*4+0], s1 = slot_of[t*4+1], s2 = slot_of[t*4+2], s3 = slot_of[t*4+3];
    float w0 = rw[t*4+0], w1 = rw[t*4+1], w2 = rw[t*4+2], w3 = rw[t*4+3];
    const h16* y0 = ybuf + (size_t)s0 * HDM;
    const h16* y1 = ybuf + (size_t)s1 * HDM;
    const h16* y2 = ybuf + (size_t)s2 * HDM;
    const h16* y3 = ybuf + (size_t)s3 * HDM;
    size_t base = (size_t)t * HDM;
    for (int i = threadIdx.x * 2; i < HDM; i += 512) {
        __half2 a0 = *(const __half2*)(y0 + i);
        __half2 a1 = *(const __half2*)(y1 + i);
        __half2 a2 = *(const __half2*)(y2 + i);
        __half2 a3 = *(const __half2*)(y3 + i);
        float2 rr = *(const float2*)(res + base + i);
        float o0 = rr.x + w0 * __half2float(a0.x) + w1 * __half2float(a1.x)
                        + w2 * __half2float(a2.x) + w3 * __half2float(a3.x);
        float o1 = rr.y + w0 * __half2float(a0.y) + w1 * __half2float(a1.y)
                        + w2 * __half2float(a2.y) + w3 * __half2float(a3.y);
        *(float2*)(out + base + i) = make_float2(o0, o1);
    }
}

// ========================================================================================
extern "C" void kernel_launch(void* const* d_in, const int* in_sizes, int n_in,
                              void* d_out, int out_size) {
    const float* x    = (const float*)d_in[0];
    const float* pe   = (const float*)d_in[1];
    const float* q_w  = (const float*)d_in[3];
    const float* k_w  = (const float*)d_in[4];
    const float* v_w  = (const float*)d_in[5];
    const float* o_w  = (const float*)d_in[6];
    const float* q_nw = (const float*)d_in[7];
    const float* k_nw = (const float*)d_in[8];
    const float* ln1  = (const float*)d_in[9];
    const float* ln2  = (const float*)d_in[10];
    const float* gw   = (const float*)d_in[11];
    const float* gpw  = (const float*)d_in[12];
    const float* upw  = (const float*)d_in[13];
    const float* dpw  = (const float*)d_in[14];
    float* out = (float*)d_out;

    #define SYM(T, p, s) T p; cudaGetSymbolAddress((void**)&p, s)
    SYM(h16*, wqkv_h, g_wqkv_h); SYM(h16*, wqkv_l, g_wqkv_l);
    SYM(h16*, wo_h, g_wo_h);     SYM(h16*, wo_l, g_wo_l);
    SYM(h16*, wgu_h, g_wgu_h);
    SYM(h16*, wd_h, g_wd_h);
    SYM(h16*, xn_h, g_xn_h);     SYM(h16*, xn_l, g_xn_l);
    SYM(float*, qkvlin, g_qkvlin);
    SYM(h16*, qh_h, g_qh_h);     SYM(h16*, qh_l, g_qh_l);
    SYM(h16*, kh_h, g_kh_h);     SYM(h16*, kh_l, g_kh_l);
    SYM(h16*, vt_h, g_vt_h);
    SYM(h16*, ao_h, g_ao_h);     SYM(h16*, ao_l, g_ao_l);
    SYM(float*, res, g_res);
    SYM(float*, h2f, g_h2f);
    SYM(h16*, h2_h, g_h2_h);
    SYM(h16*, gu, g_gu);
    SYM(h16*, gg_h, g_g_h);
    SYM(h16*, ybuf, g_ybuf);
    SYM(int*, tidx, g_tidx);      SYM(float*, trw, g_trw);
    SYM(int*, counts, g_counts);  SYM(int*, offs, g_offs);
    SYM(int*, token_of, g_token_of); SYM(int*, slot_of, g_slot_of);
    #undef SYM

    constexpr int SMEM3 = 2 * (4 * TILE_HALF * 2);   // 81920
    constexpr int SMEM1 = 2 * (2 * TILE_HALF * 2);   // 40960
    static bool attr_done = false;
    static cudaStream_t s2 = nullptr;
    static cudaEvent_t evF = nullptr, evO = nullptr, evJ = nullptr;
    if (!attr_done) {
        cudaFuncSetAttribute(gemm_mma<0,0,3>, cudaFuncAttributeMaxDynamicSharedMemorySize, SMEM3);
        cudaFuncSetAttribute(gemm_mma<2,0,3>, cudaFuncAttributeMaxDynamicSharedMemorySize, SMEM3);
        cudaFuncSetAttribute(gemm_mma<5,1,1>, cudaFuncAttributeMaxDynamicSharedMemorySize, SMEM1);
        cudaFuncSetAttribute(gemm_mma<5,2,1>, cudaFuncAttributeMaxDynamicSharedMemorySize, SMEM1);
        cudaFuncSetAttribute(flash_kernel, cudaFuncAttributeMaxDynamicSharedMemorySize, FSMEM);
        cudaStreamCreateWithFlags(&s2, cudaStreamNonBlocking);
        cudaEventCreateWithFlags(&evF, cudaEventDisableTiming);
        cudaEventCreateWithFlags(&evO, cudaEventDisableTiming);
        cudaEventCreateWithFlags(&evJ, cudaEventDisableTiming);
        attr_done = true;
    }

    const float scale = 0.08838834764831845f;

    // ---- main stream: QKV weight splits + ln1 ----
    size_t nq = (size_t)NH*HD*HDM, nk = (size_t)NKV*HD*HDM;
    split_kernel<<<(unsigned)((nq+4095)/4096), 256>>>(q_w, wqkv_h, wqkv_l, nq);
    split_kernel<<<(unsigned)((nk+4095)/4096), 256>>>(k_w, wqkv_h + nq, wqkv_l + nq, nk);
    split_kernel<<<(unsigned)((nk+4095)/4096), 256>>>(v_w, wqkv_h + nq + nk, wqkv_l + nq + nk, nk);
    rmsnorm_kernel<<<SQ, 256>>>(x, ln1, nullptr, xn_h, xn_l, HDM);
    cudaEventRecord(evF, 0);

    gemm_mma<0,0,3><<<dim3(QKVN/BN, SQ/BM, 1), 256, SMEM3>>>(
        xn_h, xn_l, HDM, 0, wqkv_h, wqkv_l, HDM, 0,
        qkvlin, nullptr, QKVN, 0, HDM, WSCI, nullptr, 0, nullptr, nullptr, nullptr);

    // ---- side stream: O-proj split + MoE weight splits ----
    cudaStreamWaitEvent(s2, evF, 0);
    size_t no = (size_t)HDM*NH*HD;
    split_kernel<<<(unsigned)((no+4095)/4096), 256, 0, s2>>>(o_w, wo_h, wo_l, no);
    cudaEventRecord(evO, s2);
    size_t ngu = (size_t)NE*ID*HDM;
    split_gu_kernel<<<(unsigned)((ngu+4095)/4096), 256, 0, s2>>>(gpw, upw, wgu_h);
    size_t nd = (size_t)NE*HDM*ID;
    split_kernel<<<(unsigned)((nd+4095)/4096), 256, 0, s2>>>(dpw, wd_h, nullptr, nd);
    cudaEventRecord(evJ, s2);

    norm_rope_kernel<<<dim3(SQ, NH + NKV), HD>>>(qkvlin, q_nw, k_nw, pe,
                                                 qh_h, qh_l, kh_h, kh_l);
    vtrans_kernel<<<dim3(SQ/32, HD/32, NKV), dim3(32, 8)>>>(qkvlin, vt_h);
    flash_kernel<<<dim3(SQ/128, NH), 256, FSMEM>>>(
        qh_h, qh_l, kh_h, kh_l, vt_h, ao_h, ao_l, scale);
    cudaStreamWaitEvent(0, evO, 0);
    gemm_mma<2,0,3><<<dim3(HDM/BN, SQ/BM, 1), 256, SMEM3>>>(
        ao_h, ao_l, NH*HD, 0, wo_h, wo_l, NH*HD, 0,
        res, nullptr, HDM, 0, NH*HD, WSCI, x, HDM, nullptr, nullptr, nullptr);

    // ---- MoE ----
    rmsnorm_kernel<<<SQ, 256>>>(res, ln2, h2f, h2_h, nullptr, HDM);
    gate_topk_kernel<<<SQ, 256>>>(h2f, gw, tidx, trw);
    route_kernel<<<1, 32>>>(tidx, counts, offs, token_of, slot_of);
    cudaStreamWaitEvent(0, evJ, 0);
    gemm_mma<5,1,1><<<dim3(GUN/BN, NSLOT/BM, NE), 256, SMEM1>>>(
        h2_h, nullptr, HDM, 0, wgu_h, nullptr, HDM, (long)GUN*HDM,
        nullptr, gu, GUN, 0, HDM, WSCI, nullptr, 0, counts, offs, token_of);
    silu_mul_kernel<<<NSLOT, 256>>>(gu, gg_h);
    gemm_mma<5,2,1><<<dim3(HDM/BN, NSLOT/BM, NE), 256, SMEM1>>>(
        gg_h, nullptr, ID, 0, wd_h, nullptr, ID, (long)HDM*ID,
        nullptr, ybuf, HDM, 0, ID, WSCI, nullptr, 0, counts, offs, token_of);
    combine_kernel<<<SQ, 256>>>(res, ybuf, slot_of, trw, out);
}